// round 1
// baseline (speedup 1.0000x reference)
#include <cuda_runtime.h>
#include <cstdint>

// Problem constants
#define NROWS   262144        // 128 * 2048
#define NCHUNKS 16384         // NROWS / 16
#define DIM     64
#define KCODES  512

// Output layout: [quantized 16777216 | loss 1 | indices 262144]
#define QOFF    0
#define LOSSOFF 16777216
#define IDXOFF  16777217

__device__ float g_partials[512];

// ---------------- packed f32x2 helpers ----------------
__device__ __forceinline__ unsigned long long pack2(float lo, float hi) {
    unsigned long long r;
    asm("mov.b64 %0, {%1, %2};" : "=l"(r) : "f"(lo), "f"(hi));
    return r;
}
__device__ __forceinline__ void fma2(unsigned long long& acc,
                                     unsigned long long a,
                                     unsigned long long b) {
    asm("fma.rn.f32x2 %0, %1, %2, %0;" : "+l"(acc) : "l"(a), "l"(b));
}
__device__ __forceinline__ float2 unpack2(unsigned long long v) {
    float lo, hi;
    asm("mov.b64 {%0, %1}, %2;" : "=f"(lo), "=f"(hi) : "l"(v));
    return make_float2(lo, hi);
}

// Warp tree-sum matching XLA GPU row-reduce: shuffle offsets 16,8,4,2,1.
// All lanes converge to the identical (bitwise) value.
__device__ __forceinline__ float wsum(float v) {
#pragma unroll
    for (int off = 16; off > 0; off >>= 1)
        v = __fadd_rn(v, __shfl_xor_sync(0xffffffffu, v, off));
    return v;
}

__global__ __launch_bounds__(512, 1)
void vq_main(const float* __restrict__ x,
             const float* __restrict__ W,
             float* __restrict__ out) {
    __shared__ float4 xns4[16][16];                 // 16 rows of normalized x
    __shared__ float s_mean[16], s_den[16], s_S[16];
    __shared__ unsigned long long s_min[16];
    __shared__ float s_loss[16];

    const int t    = threadIdx.x;   // thread == codeword id (0..511)
    const int lane = t & 31;
    const int w    = t >> 5;

    // ---- Load this thread's codeword row into registers, compute ||w||^2 ----
    unsigned long long wr[32];
    float B = 0.0f;
    {
        const float4* Wv = reinterpret_cast<const float4*>(W) + t * 16;
#pragma unroll
        for (int i = 0; i < 16; i++) {
            float4 v = Wv[i];
            wr[2 * i]     = pack2(v.x, v.y);
            wr[2 * i + 1] = pack2(v.z, v.w);
            B = __fadd_rn(B, __fmul_rn(v.x, v.x));
            B = __fadd_rn(B, __fmul_rn(v.y, v.y));
            B = __fadd_rn(B, __fmul_rn(v.z, v.z));
            B = __fadd_rn(B, __fmul_rn(v.w, v.w));
        }
    }

    float loss_acc = 0.0f;
    float* xns = reinterpret_cast<float*>(xns4);

    for (int chunk = blockIdx.x; chunk < NCHUNKS; chunk += gridDim.x) {
        const int row0 = chunk << 4;

        // ---------------- stats: warp w handles row row0+w ----------------
        {
            const float* xr = x + (size_t)(row0 + w) * DIM;
            const float a0 = xr[lane];
            const float a1 = xr[lane + 32];
            // mean: per-thread sequential pair, then tree; /64 is exact
            const float mean = wsum(__fadd_rn(a0, a1)) * 0.015625f;
            const float c0 = __fsub_rn(a0, mean);
            const float c1 = __fsub_rn(a1, mean);
            // unbiased variance: sum((x-mean)^2)/63, one rounded divide
            const float ss  = wsum(__fadd_rn(__fmul_rn(c0, c0), __fmul_rn(c1, c1)));
            const float den = __fadd_rn(sqrtf(__fdiv_rn(ss, 63.0f)), 1e-7f);
            const float xn0 = __fdiv_rn(c0, den);
            const float xn1 = __fdiv_rn(c1, den);
            // S = sum(xn^2), same reduce pattern
            const float S = wsum(__fadd_rn(__fmul_rn(xn0, xn0), __fmul_rn(xn1, xn1)));
            xns[w * 64 + lane]      = xn0;
            xns[w * 64 + lane + 32] = xn1;
            if (lane == 0) {
                s_mean[w] = mean; s_den[w] = den; s_S[w] = S;
                s_min[w]  = ~0ull;
            }
        }
        __syncthreads();

        // ---------------- distances: each thread = one codeword ----------------
#pragma unroll
        for (int g = 0; g < 4; ++g) {
            unsigned long long acc0 = 0ull, acc1 = 0ull, acc2 = 0ull, acc3 = 0ull;
#pragma unroll
            for (int i = 0; i < 16; i++) {
                const float4 v0 = xns4[g * 4 + 0][i];
                const float4 v1 = xns4[g * 4 + 1][i];
                const float4 v2 = xns4[g * 4 + 2][i];
                const float4 v3 = xns4[g * 4 + 3][i];
                fma2(acc0, pack2(v0.x, v0.y), wr[2 * i]);
                fma2(acc0, pack2(v0.z, v0.w), wr[2 * i + 1]);
                fma2(acc1, pack2(v1.x, v1.y), wr[2 * i]);
                fma2(acc1, pack2(v1.z, v1.w), wr[2 * i + 1]);
                fma2(acc2, pack2(v2.x, v2.y), wr[2 * i]);
                fma2(acc2, pack2(v2.z, v2.w), wr[2 * i + 1]);
                fma2(acc3, pack2(v3.x, v3.y), wr[2 * i]);
                fma2(acc3, pack2(v3.z, v3.w), wr[2 * i + 1]);
            }
            unsigned long long accs[4] = {acc0, acc1, acc2, acc3};
#pragma unroll
            for (int r = 0; r < 4; r++) {
                const float2 a  = unpack2(accs[r]);
                const float dot = __fadd_rn(a.x, a.y);
                // dist = fl( fl(S + B) - 2*dot );  dist ~ 63 > 0 so float bits are order-preserving
                const float dist = __fadd_rn(__fadd_rn(s_S[g * 4 + r], B),
                                             __fmul_rn(-2.0f, dot));
                unsigned long long key =
                    ((unsigned long long)__float_as_uint(dist) << 32) | (unsigned)t;
                // warp lexicographic min (dist, idx): first-occurrence argmin semantics
#pragma unroll
                for (int off = 16; off > 0; off >>= 1) {
                    unsigned long long o = __shfl_xor_sync(0xffffffffu, key, off);
                    key = (o < key) ? o : key;
                }
                if (lane == 0) atomicMin(&s_min[g * 4 + r], key);
            }
        }
        __syncthreads();

        // ---------------- output: warp w handles row row0+w ----------------
        {
            const int r    = row0 + w;
            const int idx  = (int)(s_min[w] & 1023ull);
            const float den  = s_den[w];
            const float mean = s_mean[w];
            const float q0 = W[idx * 64 + lane];
            const float q1 = W[idx * 64 + lane + 32];
            const float xn0 = xns[w * 64 + lane];
            const float xn1 = xns[w * 64 + lane + 32];
            // straight-through forward value: xn + fl(q - xn), then de-normalize (mul, add)
            const float e0  = __fsub_rn(q0, xn0);
            const float e1  = __fsub_rn(q1, xn1);
            const float qn0 = __fadd_rn(xn0, e0);
            const float qn1 = __fadd_rn(xn1, e1);
            float* oq = out + QOFF + (size_t)r * DIM;
            oq[lane]      = __fadd_rn(__fmul_rn(qn0, den), mean);
            oq[lane + 32] = __fadd_rn(__fmul_rn(qn1, den), mean);
            // loss partial: sum of (q - xn)^2 over the row
            const float ls = wsum(__fadd_rn(__fmul_rn(e0, e0), __fmul_rn(e1, e1)));
            if (lane == 0) {
                out[IDXOFF + r] = (float)idx;
                loss_acc += ls;
            }
        }
        __syncthreads();
    }

    // ---------------- deterministic loss partial per block ----------------
    if (lane == 0) s_loss[w] = loss_acc;
    __syncthreads();
    if (t == 0) {
        float s = 0.0f;
        for (int i = 0; i < 16; i++) s += s_loss[i];
        g_partials[blockIdx.x] = s;
    }
}

__global__ void vq_finalize(float* __restrict__ out, int nparts) {
    if (threadIdx.x == 0 && blockIdx.x == 0) {
        float s = 0.0f;
        for (int i = 0; i < nparts; i++) s += g_partials[i];
        // loss = q_latent + 0.25*e_latent = 1.25 * mean((q - xn)^2)
        out[LOSSOFF] = __fmul_rn(1.25f, __fdiv_rn(s, 16777216.0f));
    }
}

extern "C" void kernel_launch(void* const* d_in, const int* in_sizes, int n_in,
                              void* d_out, int out_size) {
    const float* x = (const float*)d_in[0];   // [128, 2048, 64] fp32
    const float* W = (const float*)d_in[1];   // [512, 64] fp32
    float* out = (float*)d_out;

    const int grid = 152;  // GB300 SM count; grid-stride over 16384 chunks
    vq_main<<<grid, 512>>>(x, W, out);
    vq_finalize<<<1, 32>>>(out, grid);
}

// round 4
// speedup vs baseline: 1.5853x; 1.5853x over previous
#include <cuda_runtime.h>
#include <cstdint>

typedef unsigned long long ull;

#define NROWS     262144          // 128 * 2048
#define TILE_ROWS 32
#define NTILES    (NROWS / TILE_ROWS)   // 8192
#define DIM       64
#define KCODES    512

// Output layout: [quantized 16777216 | loss 1 | indices 262144]
#define QOFF    0
#define LOSSOFF 16777216
#define IDXOFF  16777217

__device__ float g_partials[512];

// ---------------- packed f32x2 helpers ----------------
__device__ __forceinline__ void fma2(ull& acc, ull a, ull b) {
    asm("fma.rn.f32x2 %0, %1, %2, %0;" : "+l"(acc) : "l"(a), "l"(b));
}
__device__ __forceinline__ float2 unpack2(ull v) {
    float lo, hi;
    asm("mov.b64 {%0, %1}, %2;" : "=f"(lo), "=f"(hi) : "l"(v));
    return make_float2(lo, hi);
}

// Warp tree-sum: shuffle offsets 16,8,4,2,1 — all lanes get identical bits.
__device__ __forceinline__ float wsum(float v) {
#pragma unroll
    for (int off = 16; off > 0; off >>= 1)
        v = __fadd_rn(v, __shfl_xor_sync(0xffffffffu, v, off));
    return v;
}

// Dynamic shared memory layout (bytes):
//   W2   : 32 kpairs x 512 codes, ull  -> 131072
//   xnf  : 32 rows x 64 dims, float    -> 8192
//   B_s  : 512 floats                  -> 2048
//   s_mean/s_den/s_S : 32 floats each  -> 384
//   s_min: 32 ull                      -> 256
//   s_loss: 16 floats                  -> 64
#define SMEM_BYTES (131072 + 8192 + 2048 + 384 + 256 + 64)

__global__ __launch_bounds__(512, 1)
void vq_main(const float* __restrict__ x,
             const float* __restrict__ W,
             float* __restrict__ out) {
    extern __shared__ char smem_raw[];
    ull*   W2     = reinterpret_cast<ull*>(smem_raw);                   // [32][512]
    float* xnf    = reinterpret_cast<float*>(smem_raw + 131072);        // [32][64]
    float* B_s    = xnf + 32 * 64;                                      // [512]
    float* s_mean = B_s + 512;                                          // [32]
    float* s_den  = s_mean + 32;
    float* s_S    = s_den + 32;
    ull*   s_min  = reinterpret_cast<ull*>(s_S + 32);                   // [32]
    float* s_loss = reinterpret_cast<float*>(s_min + 32);               // [16]

    const int t    = threadIdx.x;
    const int lane = t & 31;
    const int w    = t >> 5;    // warp id 0..15
    const int rg   = t >> 7;    // row group 0..3 (8 rows each)
    const int cg   = t & 127;   // code group 0..127 (codes cg+128j)

    // ---- Fill W2 (k-pair-major packed layout) once per block ----
    {
        float* W2f = reinterpret_cast<float*>(W2);
        for (int idx = t; idx < KCODES * DIM; idx += 512) {
            const int c = idx >> 6;
            const int k = idx & 63;
            W2f[(k >> 1) * 1024 + 2 * c + (k & 1)] = W[idx];
        }
    }
    __syncthreads();

    // ---- B[c] = ||w_c||^2, accumulated in ascending-k order (bit-exact) ----
    {
        float b = 0.0f;
#pragma unroll 8
        for (int p = 0; p < 32; p++) {
            const float2 f = unpack2(W2[p * 512 + t]);
            b = __fadd_rn(b, __fmul_rn(f.x, f.x));
            b = __fadd_rn(b, __fmul_rn(f.y, f.y));
        }
        B_s[t] = b;
    }
    __syncthreads();

    float loss_acc = 0.0f;

    for (int tile = blockIdx.x; tile < NTILES; tile += gridDim.x) {
        const int row0 = tile * TILE_ROWS;

        // ---------------- stats: warp w handles rows 2w, 2w+1 ----------------
#pragma unroll
        for (int rr = 0; rr < 2; rr++) {
            const int row = 2 * w + rr;
            const float* xr = x + (size_t)(row0 + row) * DIM;
            const float a0 = xr[lane];
            const float a1 = xr[lane + 32];
            const float mean = wsum(__fadd_rn(a0, a1)) * 0.015625f;
            const float c0 = __fsub_rn(a0, mean);
            const float c1 = __fsub_rn(a1, mean);
            const float ss  = wsum(__fadd_rn(__fmul_rn(c0, c0), __fmul_rn(c1, c1)));
            const float den = __fadd_rn(sqrtf(__fdiv_rn(ss, 63.0f)), 1e-7f);
            const float xn0 = __fdiv_rn(c0, den);
            const float xn1 = __fdiv_rn(c1, den);
            const float S = wsum(__fadd_rn(__fmul_rn(xn0, xn0), __fmul_rn(xn1, xn1)));
            xnf[row * 64 + lane]      = xn0;
            xnf[row * 64 + lane + 32] = xn1;
            if (lane == 0) { s_mean[row] = mean; s_den[row] = den; s_S[row] = S; }
        }
        if (t < 32) s_min[t] = ~0ull;
        __syncthreads();

        // ---------------- GEMM: 8 rows x 4 codes per thread ----------------
        ull acc[8][4];
#pragma unroll
        for (int r = 0; r < 8; r++)
#pragma unroll
            for (int j = 0; j < 4; j++) acc[r][j] = 0ull;

        const ull* xrow = reinterpret_cast<const ull*>(xnf) + rg * 8 * 32;

#pragma unroll 8
        for (int p = 0; p < 32; p++) {
            ull xp[8];
#pragma unroll
            for (int r = 0; r < 8; r++) xp[r] = xrow[r * 32 + p];   // broadcast
            ull wp[4];
#pragma unroll
            for (int j = 0; j < 4; j++) wp[j] = W2[p * 512 + cg + 128 * j];
#pragma unroll
            for (int r = 0; r < 8; r++)
#pragma unroll
                for (int j = 0; j < 4; j++) fma2(acc[r][j], xp[r], wp[j]);
        }

        // ---------------- epilogue: distances + argmin ----------------
#pragma unroll
        for (int r = 0; r < 8; r++) {
            const float S = s_S[rg * 8 + r];
            ull best = ~0ull;
#pragma unroll
            for (int j = 0; j < 4; j++) {
                const int c = cg + 128 * j;
                const float2 a = unpack2(acc[r][j]);
                const float dot = __fadd_rn(a.x, a.y);
                const float dist = __fadd_rn(__fadd_rn(S, B_s[c]),
                                             __fmul_rn(-2.0f, dot));
                const ull key = ((ull)__float_as_uint(dist) << 32) | (unsigned)c;
                best = (key < best) ? key : best;
            }
#pragma unroll
            for (int off = 16; off > 0; off >>= 1) {
                const ull o = __shfl_xor_sync(0xffffffffu, best, off);
                best = (o < best) ? o : best;
            }
            if (lane == 0) atomicMin(&s_min[rg * 8 + r], best);
        }
        __syncthreads();

        // ---------------- output: warp w handles rows 2w, 2w+1 ----------------
#pragma unroll
        for (int rr = 0; rr < 2; rr++) {
            const int row = 2 * w + rr;
            const int gr  = row0 + row;
            const int idx = (int)(s_min[row] & 1023ull);
            const float den  = s_den[row];
            const float mean = s_mean[row];
            const float q0 = W[idx * 64 + lane];
            const float q1 = W[idx * 64 + lane + 32];
            const float xn0 = xnf[row * 64 + lane];
            const float xn1 = xnf[row * 64 + lane + 32];
            const float e0  = __fsub_rn(q0, xn0);
            const float e1  = __fsub_rn(q1, xn1);
            const float qn0 = __fadd_rn(xn0, e0);
            const float qn1 = __fadd_rn(xn1, e1);
            float* oq = out + QOFF + (size_t)gr * DIM;
            oq[lane]      = __fadd_rn(__fmul_rn(qn0, den), mean);
            oq[lane + 32] = __fadd_rn(__fmul_rn(qn1, den), mean);
            const float ls = wsum(__fadd_rn(__fmul_rn(e0, e0), __fmul_rn(e1, e1)));
            if (lane == 0) {
                out[IDXOFF + gr] = (float)idx;
                loss_acc += ls;
            }
        }
        __syncthreads();
    }

    // ---------------- deterministic loss partial per block ----------------
    if (lane == 0) s_loss[w] = loss_acc;
    __syncthreads();
    if (t == 0) {
        float s = 0.0f;
        for (int i = 0; i < 16; i++) s += s_loss[i];
        g_partials[blockIdx.x] = s;
    }
}

__global__ void vq_finalize(float* __restrict__ out, int nparts) {
    if (threadIdx.x == 0 && blockIdx.x == 0) {
        float s = 0.0f;
        for (int i = 0; i < nparts; i++) s += g_partials[i];
        out[LOSSOFF] = __fmul_rn(1.25f, __fdiv_rn(s, 16777216.0f));
    }
}

extern "C" void kernel_launch(void* const* d_in, const int* in_sizes, int n_in,
                              void* d_out, int out_size) {
    const float* x = (const float*)d_in[0];   // [128, 2048, 64] fp32
    const float* W = (const float*)d_in[1];   // [512, 64] fp32
    float* out = (float*)d_out;

    cudaFuncSetAttribute(vq_main, cudaFuncAttributeMaxDynamicSharedMemorySize,
                         SMEM_BYTES);

    const int grid = 152;
    vq_main<<<grid, 512, SMEM_BYTES>>>(x, W, out);
    vq_finalize<<<1, 32>>>(out, grid);
}

// round 7
// speedup vs baseline: 2.4154x; 1.5236x over previous
#include <cuda_runtime.h>
#include <cstdint>

typedef unsigned long long ull;

#define NROWS     262144            // 128 * 2048
#define TILE_ROWS 64
#define NTILES    (NROWS / TILE_ROWS)   // 4096
#define DIM       64
#define KCODES    512
#define GRID      152

// Output layout: [quantized 16777216 | loss 1 | indices 262144]
#define QOFF    0
#define LOSSOFF 16777216
#define IDXOFF  16777217

#define XSTRIDE 68    // padded row stride (floats) -> conflict-free MMA-fragment LDS
#define WSTRIDE 68

__device__ float        g_partials[GRID];
__device__ unsigned int g_count;   // zero-init; reset by last block each launch

// Warp tree-sum: offsets 16,8,4,2,1 — all lanes identical bits (unchanged from passing kernel).
__device__ __forceinline__ float wsum(float v) {
#pragma unroll
    for (int off = 16; off > 0; off >>= 1)
        v = __fadd_rn(v, __shfl_xor_sync(0xffffffffu, v, off));
    return v;
}

// m16n8k8 TF32 MMA, fp32 accumulate, acc in-place.
__device__ __forceinline__ void mma8(float c[4],
                                     uint32_t a0, uint32_t a1, uint32_t a2, uint32_t a3,
                                     uint32_t b0, uint32_t b1) {
    asm volatile(
        "mma.sync.aligned.m16n8k8.row.col.f32.tf32.tf32.f32 "
        "{%0,%1,%2,%3}, {%4,%5,%6,%7}, {%8,%9}, {%0,%1,%2,%3};"
        : "+f"(c[0]), "+f"(c[1]), "+f"(c[2]), "+f"(c[3])
        : "r"(a0), "r"(a1), "r"(a2), "r"(a3), "r"(b0), "r"(b1));
}

// Exact hi/lo split at 13 mantissa bits: v = hi + lo exactly; hi is tf32-exact,
// lo has <=13 significant bits (HW truncates to tf32's 11 -> residual ~2^-24).
__device__ __forceinline__ void split(float v, uint32_t& hi, uint32_t& lo) {
    const uint32_t h = __float_as_uint(v) & 0xFFFFE000u;
    hi = h;
    lo = __float_as_uint(__fsub_rn(v, __uint_as_float(h)));
}

// Dynamic smem (floats): Wsm 512*68 | xnf 64*68 | B_s 512 | mean/den/S 64 ea | s_min 64 ull | s_loss 16 | s_last
#define SMEM_FLOATS (KCODES*WSTRIDE + TILE_ROWS*XSTRIDE + 512 + 192 + 128 + 16 + 4)
#define SMEM_BYTES  (SMEM_FLOATS * 4)

__global__ __launch_bounds__(512, 1)
void vq_main(const float* __restrict__ x,
             const float* __restrict__ W,
             float* __restrict__ out) {
    extern __shared__ char sraw[];
    float* Wsm    = reinterpret_cast<float*>(sraw);            // [512][68]
    float* xnf    = Wsm + KCODES * WSTRIDE;                    // [64][68]
    float* B_s    = xnf + TILE_ROWS * XSTRIDE;                 // [512]
    float* s_mean = B_s + KCODES;                              // [64]
    float* s_den  = s_mean + 64;
    float* s_S    = s_den + 64;
    ull*   s_min  = reinterpret_cast<ull*>(s_S + 64);          // [64]
    float* s_loss = reinterpret_cast<float*>(s_min + 64);      // [16]
    int*   s_last = reinterpret_cast<int*>(s_loss + 16);

    const int t    = threadIdx.x;
    const int lane = t & 31;
    const int w    = t >> 5;          // warp 0..15
    const int gid  = lane >> 2;       // 0..7
    const int tig  = lane & 3;        // 0..3
    const int rb   = w & 3;           // row block (16 rows)
    const int cq   = (w >> 2) * 128;  // code quarter base

    // ---- Stage W into padded shared (coalesced) ----
    for (int idx = t; idx < KCODES * DIM; idx += 512)
        Wsm[(idx >> 6) * WSTRIDE + (idx & 63)] = W[idx];
    __syncthreads();

    // ---- B[c] = ||w_c||^2, ascending-k single accumulator (bit-exact vs prior rounds) ----
    {
        float b = 0.0f;
        const float* wr = Wsm + t * WSTRIDE;
#pragma unroll 16
        for (int k = 0; k < 64; k++)
            b = __fadd_rn(b, __fmul_rn(wr[k], wr[k]));
        B_s[t] = b;
    }
    __syncthreads();

    float loss_acc = 0.0f;

    for (int tile = blockIdx.x; tile < NTILES; tile += gridDim.x) {
        const int row0 = tile * TILE_ROWS;

        // ---------------- stats: warp w handles rows 4w..4w+3 ----------------
#pragma unroll
        for (int rr = 0; rr < 4; rr++) {
            const int row = 4 * w + rr;
            const float* xr = x + (size_t)(row0 + row) * DIM;
            const float a0 = xr[lane];
            const float a1 = xr[lane + 32];
            const float mean = wsum(__fadd_rn(a0, a1)) * 0.015625f;
            const float c0 = __fsub_rn(a0, mean);
            const float c1 = __fsub_rn(a1, mean);
            const float ss  = wsum(__fadd_rn(__fmul_rn(c0, c0), __fmul_rn(c1, c1)));
            const float den = __fadd_rn(sqrtf(__fdiv_rn(ss, 63.0f)), 1e-7f);
            const float xn0 = __fdiv_rn(c0, den);
            const float xn1 = __fdiv_rn(c1, den);
            const float S = wsum(__fadd_rn(__fmul_rn(xn0, xn0), __fmul_rn(xn1, xn1)));
            xnf[row * XSTRIDE + lane]      = xn0;
            xnf[row * XSTRIDE + lane + 32] = xn1;
            if (lane == 0) {
                s_mean[row] = mean; s_den[row] = den; s_S[row] = S;
                s_min[row]  = ~0ull;
            }
        }
        __syncthreads();

        // ---------------- A fragments: 16 rows x K=64, hi/lo split ----------------
        uint32_t ah[8][4], al[8][4];
        {
            const float* p0 = xnf + (rb * 16 + gid) * XSTRIDE + tig;
            const float* p1 = p0 + 8 * XSTRIDE;
#pragma unroll
            for (int kt = 0; kt < 8; kt++) {
                split(p0[kt * 8],     ah[kt][0], al[kt][0]);
                split(p1[kt * 8],     ah[kt][1], al[kt][1]);
                split(p0[kt * 8 + 4], ah[kt][2], al[kt][2]);
                split(p1[kt * 8 + 4], ah[kt][3], al[kt][3]);
            }
        }

        ull best_lo = ~0ull, best_hi = ~0ull;
        const int   row_lo = rb * 16 + gid;
        const float Slo = s_S[row_lo];
        const float Shi = s_S[row_lo + 8];

        // ---------------- 16 n-tiles (8 codes each), 2 at a time ----------------
#pragma unroll 1
        for (int p = 0; p < 8; p++) {
            float chh0[4] = {0, 0, 0, 0}, clo0[4] = {0, 0, 0, 0};
            float chh1[4] = {0, 0, 0, 0}, clo1[4] = {0, 0, 0, 0};
            const float* b0p = Wsm + (cq + (2 * p) * 8 + gid) * WSTRIDE + tig;
            const float* b1p = b0p + 8 * WSTRIDE;
#pragma unroll
            for (int kt = 0; kt < 8; kt++) {
                uint32_t bh0a, bl0a, bh0b, bl0b, bh1a, bl1a, bh1b, bl1b;
                split(b0p[kt * 8],     bh0a, bl0a);
                split(b0p[kt * 8 + 4], bh0b, bl0b);
                split(b1p[kt * 8],     bh1a, bl1a);
                split(b1p[kt * 8 + 4], bh1b, bl1b);
                mma8(clo0, al[kt][0], al[kt][1], al[kt][2], al[kt][3], bh0a, bh0b);
                mma8(clo0, ah[kt][0], ah[kt][1], ah[kt][2], ah[kt][3], bl0a, bl0b);
                mma8(chh0, ah[kt][0], ah[kt][1], ah[kt][2], ah[kt][3], bh0a, bh0b);
                mma8(clo1, al[kt][0], al[kt][1], al[kt][2], al[kt][3], bh1a, bh1b);
                mma8(clo1, ah[kt][0], ah[kt][1], ah[kt][2], ah[kt][3], bl1a, bl1b);
                mma8(chh1, ah[kt][0], ah[kt][1], ah[kt][2], ah[kt][3], bh1a, bh1b);
            }
            // epilogue: distances + running lexicographic min
#pragma unroll
            for (int u = 0; u < 2; u++) {
                const float* chh = u ? chh1 : chh0;
                const float* clo = u ? clo1 : clo0;
                const int cbase = cq + (2 * p + u) * 8 + 2 * tig;
                const float B0 = B_s[cbase], B1 = B_s[cbase + 1];
                float d;
                d = __fadd_rn(__fadd_rn(Slo, B0), __fmul_rn(-2.0f, __fadd_rn(chh[0], clo[0])));
                const ull k0 = ((ull)__float_as_uint(d) << 32) | (unsigned)cbase;
                d = __fadd_rn(__fadd_rn(Slo, B1), __fmul_rn(-2.0f, __fadd_rn(chh[1], clo[1])));
                const ull k1 = ((ull)__float_as_uint(d) << 32) | (unsigned)(cbase + 1);
                d = __fadd_rn(__fadd_rn(Shi, B0), __fmul_rn(-2.0f, __fadd_rn(chh[2], clo[2])));
                const ull k2 = ((ull)__float_as_uint(d) << 32) | (unsigned)cbase;
                d = __fadd_rn(__fadd_rn(Shi, B1), __fmul_rn(-2.0f, __fadd_rn(chh[3], clo[3])));
                const ull k3 = ((ull)__float_as_uint(d) << 32) | (unsigned)(cbase + 1);
                if (k0 < best_lo) best_lo = k0;
                if (k1 < best_lo) best_lo = k1;
                if (k2 < best_hi) best_hi = k2;
                if (k3 < best_hi) best_hi = k3;
            }
        }

        // reduce (dist,idx) min across the 4-lane group, then across warps
        {
            ull o;
            o = __shfl_xor_sync(0xffffffffu, best_lo, 1); if (o < best_lo) best_lo = o;
            o = __shfl_xor_sync(0xffffffffu, best_lo, 2); if (o < best_lo) best_lo = o;
            o = __shfl_xor_sync(0xffffffffu, best_hi, 1); if (o < best_hi) best_hi = o;
            o = __shfl_xor_sync(0xffffffffu, best_hi, 2); if (o < best_hi) best_hi = o;
            if (tig == 0) {
                atomicMin(&s_min[row_lo],     best_lo);
                atomicMin(&s_min[row_lo + 8], best_hi);
            }
        }
        __syncthreads();

        // ---------------- output: warp w handles rows 4w..4w+3 ----------------
#pragma unroll
        for (int rr = 0; rr < 4; rr++) {
            const int row = 4 * w + rr;
            const int gr  = row0 + row;
            const int idx = (int)(s_min[row] & 1023ull);
            const float den  = s_den[row];
            const float mean = s_mean[row];
            const float q0 = W[idx * 64 + lane];
            const float q1 = W[idx * 64 + lane + 32];
            const float xn0 = xnf[row * XSTRIDE + lane];
            const float xn1 = xnf[row * XSTRIDE + lane + 32];
            const float e0  = __fsub_rn(q0, xn0);
            const float e1  = __fsub_rn(q1, xn1);
            const float qn0 = __fadd_rn(xn0, e0);
            const float qn1 = __fadd_rn(xn1, e1);
            float* oq = out + QOFF + (size_t)gr * DIM;
            oq[lane]      = __fadd_rn(__fmul_rn(qn0, den), mean);
            oq[lane + 32] = __fadd_rn(__fmul_rn(qn1, den), mean);
            const float ls = wsum(__fadd_rn(__fmul_rn(e0, e0), __fmul_rn(e1, e1)));
            if (lane == 0) {
                out[IDXOFF + gr] = (float)idx;
                loss_acc += ls;
            }
        }
        __syncthreads();
    }

    // ---------------- fused deterministic loss finalize (last-block) ----------------
    if (lane == 0) s_loss[w] = loss_acc;
    __syncthreads();
    if (t == 0) {
        float s = 0.0f;
        for (int i = 0; i < 16; i++) s += s_loss[i];
        g_partials[blockIdx.x] = s;
        __threadfence();
        const unsigned tick = atomicAdd(&g_count, 1u);
        *s_last = (tick == gridDim.x - 1);
    }
    __syncthreads();
    if (t == 0 && *s_last) {
        __threadfence();
        float s = 0.0f;
        for (int i = 0; i < (int)gridDim.x; i++) s += g_partials[i];
        out[LOSSOFF] = __fmul_rn(1.25f, __fdiv_rn(s, 16777216.0f));
        g_count = 0;   // reset for next graph replay
    }
}

extern "C" void kernel_launch(void* const* d_in, const int* in_sizes, int n_in,
                              void* d_out, int out_size) {
    const float* x = (const float*)d_in[0];   // [128, 2048, 64] fp32
    const float* W = (const float*)d_in[1];   // [512, 64] fp32
    float* out = (float*)d_out;

    cudaFuncSetAttribute(vq_main, cudaFuncAttributeMaxDynamicSharedMemorySize,
                         SMEM_BYTES);
    vq_main<<<GRID, 512, SMEM_BYTES>>>(x, W, out);
}